// round 1
// baseline (speedup 1.0000x reference)
#include <cuda_runtime.h>

// Problem constants
#define BATCH 2
#define CHAN  128
#define NGRP  16
#define CPG   8      // channels per group (128/16)
#define HH    64
#define WW    64
#define HW    (HH*WW)
#define NP    81     // 9x9 displacements
#define NDIL  4

// Conv tile
#define TILE_H 8
#define TILE_W 32
#define SIN_H  (TILE_H + 2)   // 10
#define SIN_W  (TILE_W + 2)   // 34
#define SIN_ELEMS (NGRP * 3 * SIN_H * SIN_W)   // 16*3*10*34 = 16320
#define SW_ELEMS  (NGRP * NGRP * 27)           // 6912
#define SMEM_FLOATS (SIN_ELEMS + SW_ELEMS + 32)
#define SMEM_BYTES  (SMEM_FLOATS * 4)

// Scratch cost volume: [dil][b][g][disp][h][w]  = 4*2*16*81*4096 floats = ~170MB
__device__ float g_cost[(size_t)NDIL * BATCH * NGRP * NP * HW];

// ---------------------------------------------------------------------------
// Kernel 1: grouped windowed correlation + leaky ReLU(0.1)
// grid: (H/4, NGRP, NDIL*BATCH), block: (64, 4)
// ---------------------------------------------------------------------------
__global__ void corr_kernel(const float* __restrict__ x,
                            const float* __restrict__ nb) {
    const int w  = threadIdx.x;               // 0..63
    const int h  = blockIdx.x * 4 + threadIdx.y;
    const int g  = blockIdx.y;
    const int zb = blockIdx.z;                // dil*BATCH + b
    const int dil_idx = zb >> 1;
    const int b  = zb & 1;
    const int dil = 1 << dil_idx;             // 1,2,4,8

    // x1 values for this pixel: channels g, g+16, ..., g+112
    float a1[CPG];
#pragma unroll
    for (int c = 0; c < CPG; c++)
        a1[c] = x[(size_t)(b * CHAN + c * NGRP + g) * HW + h * WW + w];

    const float* __restrict__ x2b = nb + (size_t)b * CHAN * HW;
    float* __restrict__ outp =
        g_cost + ((size_t)(zb * NGRP + g) * NP) * HW + h * WW + w;

#pragma unroll 1
    for (int di = 0; di < 9; di++) {
        const int y = h + (di - 4) * dil;
        const bool yok = ((unsigned)y < HH);
#pragma unroll 1
        for (int dj = 0; dj < 9; dj++) {
            const int xw = w + (dj - 4) * dil;
            float s = 0.f;
            if (yok && (unsigned)xw < WW) {
                const int off = y * WW + xw;
#pragma unroll
                for (int c = 0; c < CPG; c++)
                    s += a1[c] * x2b[(size_t)(c * NGRP + g) * HW + off];
            }
            // leaky relu 0.1
            s = (s > 0.f) ? s : 0.1f * s;
            outp[(size_t)(di * 9 + dj) * HW] = s;
        }
    }
}

// ---------------------------------------------------------------------------
// Kernel 2: 3x3x3 grouped conv (16->16) + bias + BN(eval) + ReLU, writes out
// grid: (W/TILE_W=2, H/TILE_H=8, NDIL*BATCH*NP=648), block: 256 threads
// ---------------------------------------------------------------------------
__global__ void conv_kernel(const float* __restrict__ conv_w,
                            const float* __restrict__ conv_b,
                            const float* __restrict__ bn_gamma,
                            const float* __restrict__ bn_beta,
                            const float* __restrict__ bn_mean,
                            const float* __restrict__ bn_var,
                            float* __restrict__ out) {
    extern __shared__ float sm[];
    float* s_in = sm;                       // [16][3][SIN_H][SIN_W]
    float* s_w  = sm + SIN_ELEMS;           // [gin*27+tap][16 gout]
    float* s_sc = s_w + SW_ELEMS;           // [16]
    float* s_sh = s_sc + 16;                // [16]

    const int tid = threadIdx.x;            // 0..255
    const int zb  = blockIdx.z;
    const int dil_idx = zb / (BATCH * NP);
    const int rem = zb % (BATCH * NP);
    const int b   = rem / NP;
    const int d   = rem % NP;
    const int h0  = blockIdx.y * TILE_H;
    const int w0  = blockIdx.x * TILE_W;

    const float* __restrict__ cost =
        g_cost + (size_t)(dil_idx * BATCH + b) * NGRP * NP * HW;

    // --- stage input halo tile [16 gin][3 kd][10][34] ---
    for (int i = tid; i < SIN_ELEMS; i += 256) {
        int wi = i % SIN_W;
        int t  = i / SIN_W;
        int hi = t % SIN_H;
        t /= SIN_H;
        int kd  = t % 3;
        int gin = t / 3;
        int dg = d + kd - 1;
        int hg = h0 + hi - 1;
        int wg = w0 + wi - 1;
        float v = 0.f;
        if ((unsigned)dg < NP && (unsigned)hg < HH && (unsigned)wg < WW)
            v = cost[(size_t)gin * (NP * HW) + (size_t)dg * HW + hg * WW + wg];
        s_in[i] = v;
    }

    // --- stage weights, transposed so gout is innermost (LDS.128-friendly) ---
    const float* __restrict__ wsrc = conv_w + (size_t)dil_idx * SW_ELEMS;
    for (int i = tid; i < SW_ELEMS; i += 256) {
        int gout = i / (NGRP * 27);
        int gt   = i % (NGRP * 27);   // gin*27 + tap
        s_w[gt * NGRP + gout] = wsrc[i];
    }

    // --- fold conv bias + BN into scale/shift ---
    if (tid < NGRP) {
        int gi = dil_idx * NGRP + tid;
        float inv = bn_gamma[gi] * rsqrtf(bn_var[gi] + 1e-5f);
        s_sc[tid] = inv;
        s_sh[tid] = (conv_b[gi] - bn_mean[gi]) * inv + bn_beta[gi];
    }
    __syncthreads();

    const int tx = tid & 31;
    const int ty = tid >> 5;

    float acc[NGRP];
#pragma unroll
    for (int i = 0; i < NGRP; i++) acc[i] = 0.f;

#pragma unroll 1
    for (int gin = 0; gin < NGRP; gin++) {
        const float* __restrict__ in_g = s_in + gin * (3 * SIN_H * SIN_W);
        const float* __restrict__ w_g  = s_w + gin * 27 * NGRP;
#pragma unroll
        for (int kd = 0; kd < 3; kd++) {
#pragma unroll
            for (int kh = 0; kh < 3; kh++) {
#pragma unroll
                for (int kw = 0; kw < 3; kw++) {
                    const float v =
                        in_g[kd * (SIN_H * SIN_W) + (ty + kh) * SIN_W + tx + kw];
                    const float4* wp =
                        (const float4*)(w_g + (kd * 9 + kh * 3 + kw) * NGRP);
#pragma unroll
                    for (int q = 0; q < 4; q++) {
                        float4 wv = wp[q];
                        acc[q * 4 + 0] = fmaf(v, wv.x, acc[q * 4 + 0]);
                        acc[q * 4 + 1] = fmaf(v, wv.y, acc[q * 4 + 1]);
                        acc[q * 4 + 2] = fmaf(v, wv.z, acc[q * 4 + 2]);
                        acc[q * 4 + 3] = fmaf(v, wv.w, acc[q * 4 + 3]);
                    }
                }
            }
        }
    }

    // --- epilogue: scale/shift + ReLU, write output ---
    const int h = h0 + ty;
    const int w = w0 + tx;
    const size_t obase =
        ((size_t)(b * (NDIL * NGRP) + dil_idx * NGRP) * NP + d) * HW + h * WW + w;
#pragma unroll
    for (int go = 0; go < NGRP; go++) {
        float z = acc[go] * s_sc[go] + s_sh[go];
        out[obase + (size_t)go * (NP * HW)] = fmaxf(z, 0.f);
    }
}

// ---------------------------------------------------------------------------
extern "C" void kernel_launch(void* const* d_in, const int* in_sizes, int n_in,
                              void* d_out, int out_size) {
    const float* x  = (const float*)d_in[0];
    const float* nb = (const float*)d_in[1];
    const float* cw = (const float*)d_in[2];
    const float* cb = (const float*)d_in[3];
    const float* gm = (const float*)d_in[4];
    const float* bt = (const float*)d_in[5];
    const float* mn = (const float*)d_in[6];
    const float* vr = (const float*)d_in[7];
    float* out = (float*)d_out;

    // correlation + leaky relu -> g_cost
    dim3 cb1(64, 4);
    dim3 cg1(HH / 4, NGRP, NDIL * BATCH);
    corr_kernel<<<cg1, cb1>>>(x, nb);

    // conv3d + bias + bn + relu -> out
    cudaFuncSetAttribute(conv_kernel,
                         cudaFuncAttributeMaxDynamicSharedMemorySize,
                         SMEM_BYTES);
    dim3 cg2(WW / TILE_W, HH / TILE_H, NDIL * BATCH * NP);
    conv_kernel<<<cg2, 256, SMEM_BYTES>>>(cw, cb, gm, bt, mn, vr, out);
}

// round 2
// speedup vs baseline: 1.9411x; 1.9411x over previous
#include <cuda_runtime.h>

// Problem constants
#define BATCH 2
#define CHAN  128
#define NGRP  16
#define CPG   8
#define HH    64
#define WW    64
#define HW    (HH*WW)
#define NP    81
#define NDIL  4
#define NPHW  (NP*HW)

// Conv tiling: full width, 8 rows per block, 2 pixels per thread (rows ty, ty+4)
#define TILE_H 8
#define SIN_H  (TILE_H + 2)       // 10
#define SIN_W  (WW + 2)           // 66
#define SLAB   (3 * SIN_H * SIN_W)  // per-gin input slab: 1980 floats
#define SW_ELEMS (NGRP * NGRP * 27) // 6912

// Scratch cost volume: [dil*b][g][disp][h][w] ~170MB
__device__ float g_cost[(size_t)NDIL * BATCH * NGRP * NPHW];

// packed fp32x2 helpers (Blackwell f32x2 pipe: 2 FMAs per issue slot)
__device__ __forceinline__ unsigned long long pack_dup(float v) {
    unsigned long long r;
    asm("mov.b64 %0, {%1, %1};" : "=l"(r) : "f"(v));
    return r;
}
__device__ __forceinline__ unsigned long long ffma2(
    unsigned long long a, unsigned long long b, unsigned long long c) {
    unsigned long long d;
    asm("fma.rn.f32x2 %0, %1, %2, %3;" : "=l"(d) : "l"(a), "l"(b), "l"(c));
    return d;
}

// ---------------------------------------------------------------------------
// Kernel 1: grouped windowed correlation + leaky ReLU(0.1)
// ---------------------------------------------------------------------------
__global__ void corr_kernel(const float* __restrict__ x,
                            const float* __restrict__ nb) {
    const int w  = threadIdx.x;
    const int h  = blockIdx.x * 4 + threadIdx.y;
    const int g  = blockIdx.y;
    const int zb = blockIdx.z;
    const int b  = zb & 1;
    const int dil = 1 << (zb >> 1);

    float a1[CPG];
#pragma unroll
    for (int c = 0; c < CPG; c++)
        a1[c] = x[(size_t)(b * CHAN + c * NGRP + g) * HW + h * WW + w];

    const float* __restrict__ x2b = nb + (size_t)b * CHAN * HW;
    float* __restrict__ outp =
        g_cost + ((size_t)(zb * NGRP + g) * NP) * HW + h * WW + w;

#pragma unroll 1
    for (int di = 0; di < 9; di++) {
        const int y = h + (di - 4) * dil;
        const bool yok = ((unsigned)y < HH);
#pragma unroll 1
        for (int dj = 0; dj < 9; dj++) {
            const int xw = w + (dj - 4) * dil;
            float s = 0.f;
            if (yok && (unsigned)xw < WW) {
                const int off = y * WW + xw;
#pragma unroll
                for (int c = 0; c < CPG; c++)
                    s += a1[c] * x2b[(size_t)(c * NGRP + g) * HW + off];
            }
            s = (s > 0.f) ? s : 0.1f * s;
            outp[(size_t)(di * 9 + dj) * HW] = s;
        }
    }
}

// ---------------------------------------------------------------------------
// Kernel 2: 3x3x3 grouped conv (16->16) + bias + BN + ReLU, packed f32x2
// grid: (1, HH/TILE_H=8, NDIL*BATCH*NP=648), block (64,4)=256
// ---------------------------------------------------------------------------
__global__ void __launch_bounds__(256, 3)
conv_kernel(const float* __restrict__ conv_w,
            const float* __restrict__ conv_b,
            const float* __restrict__ bn_gamma,
            const float* __restrict__ bn_beta,
            const float* __restrict__ bn_mean,
            const float* __restrict__ bn_var,
            float* __restrict__ out) {
    __shared__ float s_in[2][SLAB];          // double-buffered per-gin slab
    __shared__ float s_w[SW_ELEMS];          // [gin*27+tap][16 gout]
    __shared__ float s_sc[NGRP], s_sh[NGRP];

    const int tx  = threadIdx.x;             // 0..63
    const int ty  = threadIdx.y;              // 0..3
    const int tid = ty * 64 + tx;
    const int zb  = blockIdx.z;
    const int dil_idx = zb / (BATCH * NP);
    const int rem = zb % (BATCH * NP);
    const int b   = rem / NP;
    const int d   = rem % NP;
    const int h0  = blockIdx.y * TILE_H;

    const float* __restrict__ costz =
        g_cost + (size_t)(dil_idx * BATCH + b) * NGRP * NPHW;

    // Precompute the 8 staging offsets this thread uses for every gin slab.
    int gofs[8];
#pragma unroll
    for (int k = 0; k < 8; k++) {
        int i = tid + k * 256;
        int ofs = -1;
        if (i < SLAB) {
            int kd = i / (SIN_H * SIN_W);
            int r  = i - kd * (SIN_H * SIN_W);
            int hi = r / SIN_W;
            int wi = r - hi * SIN_W;
            int dg = d + kd - 1;
            int hg = h0 + hi - 1;
            int wg = wi - 1;
            if ((unsigned)dg < NP && (unsigned)hg < HH && (unsigned)wg < WW)
                ofs = dg * HW + hg * WW + wg;
        }
        gofs[k] = ofs;
    }

    // Stage weights transposed: [gin*27+tap][gout]
    const float* __restrict__ wsrc = conv_w + (size_t)dil_idx * SW_ELEMS;
    for (int i = tid; i < SW_ELEMS; i += 256) {
        int gout = i / (NGRP * 27);
        int gt   = i - gout * (NGRP * 27);
        s_w[gt * NGRP + gout] = wsrc[i];
    }

    // Fold conv bias + BN into scale/shift
    if (tid < NGRP) {
        int gi = dil_idx * NGRP + tid;
        float inv = bn_gamma[gi] * rsqrtf(bn_var[gi] + 1e-5f);
        s_sc[tid] = inv;
        s_sh[tid] = (conv_b[gi] - bn_mean[gi]) * inv + bn_beta[gi];
    }

    // Prologue: stage gin=0 slab into buffer 0
#pragma unroll
    for (int k = 0; k < 8; k++) {
        int i = tid + k * 256;
        if (i < SLAB)
            s_in[0][i] = (gofs[k] >= 0) ? costz[gofs[k]] : 0.f;
    }
    __syncthreads();

    // Accumulators: 16 gout as 8 f32x2 pairs, for 2 pixel rows (ty, ty+4)
    unsigned long long acc0[8], acc1[8];
#pragma unroll
    for (int i = 0; i < 8; i++) { acc0[i] = 0ull; acc1[i] = 0ull; }

#pragma unroll 1
    for (int gin = 0; gin < NGRP; gin++) {
        // Prefetch next gin slab into registers (overlap LDG with compute)
        float pf[8];
        if (gin < NGRP - 1) {
            const float* __restrict__ src = costz + (size_t)(gin + 1) * NPHW;
#pragma unroll
            for (int k = 0; k < 8; k++)
                pf[k] = (gofs[k] >= 0) ? src[gofs[k]] : 0.f;
        }

        const float* __restrict__ in_g = s_in[gin & 1];
        const float* __restrict__ w_g  = s_w + gin * 27 * NGRP;

#pragma unroll
        for (int kd = 0; kd < 3; kd++) {
#pragma unroll
            for (int kh = 0; kh < 3; kh++) {
#pragma unroll
                for (int kw = 0; kw < 3; kw++) {
                    const int base = kd * (SIN_H * SIN_W) + kh * SIN_W + tx + kw;
                    unsigned long long vv0 = pack_dup(in_g[base + ty * SIN_W]);
                    unsigned long long vv1 = pack_dup(in_g[base + (ty + 4) * SIN_W]);
                    const ulonglong2* wp =
                        (const ulonglong2*)(w_g + (kd * 9 + kh * 3 + kw) * NGRP);
#pragma unroll
                    for (int q = 0; q < 4; q++) {
                        ulonglong2 wq = wp[q];
                        acc0[q * 2 + 0] = ffma2(vv0, wq.x, acc0[q * 2 + 0]);
                        acc0[q * 2 + 1] = ffma2(vv0, wq.y, acc0[q * 2 + 1]);
                        acc1[q * 2 + 0] = ffma2(vv1, wq.x, acc1[q * 2 + 0]);
                        acc1[q * 2 + 1] = ffma2(vv1, wq.y, acc1[q * 2 + 1]);
                    }
                }
            }
        }

        // Commit prefetched slab, then barrier before next gin reads it
        if (gin < NGRP - 1) {
            float* dst = s_in[(gin + 1) & 1];
#pragma unroll
            for (int k = 0; k < 8; k++) {
                int i = tid + k * 256;
                if (i < SLAB) dst[i] = pf[k];
            }
        }
        __syncthreads();
    }

    // Epilogue: BN scale/shift + ReLU, two pixel rows
    const int h = h0 + ty;
    const size_t ob =
        ((size_t)(b * (NDIL * NGRP) + dil_idx * NGRP) * NP + d) * HW + h * WW + tx;
#pragma unroll
    for (int p = 0; p < 8; p++) {
        float lo, hi;
        asm("mov.b64 {%0, %1}, %2;" : "=f"(lo), "=f"(hi) : "l"(acc0[p]));
        float z0 = fmaxf(lo * s_sc[2 * p] + s_sh[2 * p], 0.f);
        float z1 = fmaxf(hi * s_sc[2 * p + 1] + s_sh[2 * p + 1], 0.f);
        out[ob + (size_t)(2 * p) * NPHW]     = z0;
        out[ob + (size_t)(2 * p + 1) * NPHW] = z1;
        asm("mov.b64 {%0, %1}, %2;" : "=f"(lo), "=f"(hi) : "l"(acc1[p]));
        z0 = fmaxf(lo * s_sc[2 * p] + s_sh[2 * p], 0.f);
        z1 = fmaxf(hi * s_sc[2 * p + 1] + s_sh[2 * p + 1], 0.f);
        out[ob + 4 * WW + (size_t)(2 * p) * NPHW]     = z0;
        out[ob + 4 * WW + (size_t)(2 * p + 1) * NPHW] = z1;
    }
}

// ---------------------------------------------------------------------------
extern "C" void kernel_launch(void* const* d_in, const int* in_sizes, int n_in,
                              void* d_out, int out_size) {
    const float* x  = (const float*)d_in[0];
    const float* nb = (const float*)d_in[1];
    const float* cw = (const float*)d_in[2];
    const float* cb = (const float*)d_in[3];
    const float* gm = (const float*)d_in[4];
    const float* bt = (const float*)d_in[5];
    const float* mn = (const float*)d_in[6];
    const float* vr = (const float*)d_in[7];
    float* out = (float*)d_out;

    dim3 cb1(64, 4);
    dim3 cg1(HH / 4, NGRP, NDIL * BATCH);
    corr_kernel<<<cg1, cb1>>>(x, nb);

    dim3 cg2(1, HH / TILE_H, NDIL * BATCH * NP);
    conv_kernel<<<cg2, dim3(64, 4)>>>(cw, cb, gm, bt, mn, vr, out);
}

// round 3
// speedup vs baseline: 2.1163x; 1.0903x over previous
#include <cuda_runtime.h>
#include <cstdint>

// Problem constants
#define BATCH 2
#define CHAN  128
#define NGRP  16
#define CPG   8
#define HH    64
#define WW    64
#define HW    (HH*WW)
#define NP    81
#define NDIL  4
#define NPHW  (NP*HW)

// Conv tiling: 16 rows x 64 wide per block; thread = 4 contiguous rows x 1 col
#define TILE_H 16
#define SIN_H  (TILE_H + 2)          // 18
#define SIN_W  (WW + 2)              // 66
#define SLAB   (3 * SIN_H * SIN_W)   // 3564 floats per gin slab
#define SLAB_LD 14                   // ceil(3564/256)
#define SW_ELEMS (NGRP * NGRP * 27)  // 6912

// Scratch cost volume: [dil*b][g][disp][h][w] ~170MB
__device__ float g_cost[(size_t)NDIL * BATCH * NGRP * NPHW];

// ---- packed fp32x2 helpers ----
__device__ __forceinline__ unsigned long long pack_dup(float v) {
    unsigned long long r;
    asm("mov.b64 %0, {%1, %1};" : "=l"(r) : "f"(v));
    return r;
}
__device__ __forceinline__ unsigned long long ffma2(
    unsigned long long a, unsigned long long b, unsigned long long c) {
    unsigned long long d;
    asm("fma.rn.f32x2 %0, %1, %2, %3;" : "=l"(d) : "l"(a), "l"(b), "l"(c));
    return d;
}
__device__ __forceinline__ uint32_t smem_u32(const void* p) {
    uint32_t a;
    asm("{ .reg .u64 t; cvta.to.shared.u64 t, %1; cvt.u32.u64 %0, t; }"
        : "=r"(a) : "l"(p));
    return a;
}
__device__ __forceinline__ void cp_async4(uint32_t dst, const float* src, int sz) {
    asm volatile("cp.async.ca.shared.global [%0], [%1], 4, %2;"
                 :: "r"(dst), "l"(src), "r"(sz));
}

// ---------------------------------------------------------------------------
// Kernel 1: grouped windowed correlation + leaky ReLU(0.1)
// ---------------------------------------------------------------------------
__global__ void corr_kernel(const float* __restrict__ x,
                            const float* __restrict__ nb) {
    const int w  = threadIdx.x;
    const int h  = blockIdx.x * 4 + threadIdx.y;
    const int g  = blockIdx.y;
    const int zb = blockIdx.z;
    const int b  = zb & 1;
    const int dil = 1 << (zb >> 1);

    float a1[CPG];
#pragma unroll
    for (int c = 0; c < CPG; c++)
        a1[c] = x[(size_t)(b * CHAN + c * NGRP + g) * HW + h * WW + w];

    const float* __restrict__ x2b = nb + (size_t)b * CHAN * HW;
    float* __restrict__ outp =
        g_cost + ((size_t)(zb * NGRP + g) * NP) * HW + h * WW + w;

#pragma unroll 1
    for (int di = 0; di < 9; di++) {
        const int y = h + (di - 4) * dil;
        const bool yok = ((unsigned)y < HH);
#pragma unroll 1
        for (int dj = 0; dj < 9; dj++) {
            const int xw = w + (dj - 4) * dil;
            float s = 0.f;
            if (yok && (unsigned)xw < WW) {
                const int off = y * WW + xw;
#pragma unroll
                for (int c = 0; c < CPG; c++)
                    s += a1[c] * x2b[(size_t)(c * NGRP + g) * HW + off];
            }
            s = (s > 0.f) ? s : 0.1f * s;
            outp[(size_t)(di * 9 + dj) * HW] = s;
        }
    }
}

// ---------------------------------------------------------------------------
// Kernel 2: 3x3x3 grouped conv (16->16) + bias + BN + ReLU
// f32x2 accumulators, 4 rows/thread with kh row-rotation, cp.async pipeline
// grid: (1, HH/TILE_H=4, NDIL*BATCH*NP=648), block (64,4)=256
// ---------------------------------------------------------------------------
__global__ void __launch_bounds__(256, 2)
conv_kernel(const float* __restrict__ conv_w,
            const float* __restrict__ conv_b,
            const float* __restrict__ bn_gamma,
            const float* __restrict__ bn_beta,
            const float* __restrict__ bn_mean,
            const float* __restrict__ bn_var,
            float* __restrict__ out) {
    extern __shared__ float sm[];
    float* s_in = sm;                    // [2][SLAB]
    float* s_w  = sm + 2 * SLAB;         // [gin*27+tap][16 gout]
    float* s_sc = s_w + SW_ELEMS;
    float* s_sh = s_sc + NGRP;

    const int tx  = threadIdx.x;         // 0..63
    const int ty  = threadIdx.y;         // 0..3
    const int tid = ty * 64 + tx;
    const int zb  = blockIdx.z;
    const int dil_idx = zb / (BATCH * NP);
    const int rem = zb % (BATCH * NP);
    const int b   = rem / NP;
    const int d   = rem % NP;
    const int h0  = blockIdx.y * TILE_H;

    const float* __restrict__ costz =
        g_cost + (size_t)(dil_idx * BATCH + b) * NGRP * NPHW;

    // Per-thread staging offsets (same for every gin slab)
    int gofs[SLAB_LD];
#pragma unroll
    for (int k = 0; k < SLAB_LD; k++) {
        int i = tid + k * 256;
        int ofs = -1;
        if (i < SLAB) {
            int kd = i / (SIN_H * SIN_W);
            int r  = i - kd * (SIN_H * SIN_W);
            int hi = r / SIN_W;
            int wi = r - hi * SIN_W;
            int dg = d + kd - 1;
            int hg = h0 + hi - 1;
            int wg = wi - 1;
            if ((unsigned)dg < NP && (unsigned)hg < HH && (unsigned)wg < WW)
                ofs = dg * HW + hg * WW + wg;
        }
        gofs[k] = ofs;
    }
    uint32_t s_in_addr = smem_u32(s_in);

    // Stage weights transposed: [gin*27+tap][gout]
    const float* __restrict__ wsrc = conv_w + (size_t)dil_idx * SW_ELEMS;
    for (int i = tid; i < SW_ELEMS; i += 256) {
        int gout = i / (NGRP * 27);
        int gt   = i - gout * (NGRP * 27);
        s_w[gt * NGRP + gout] = wsrc[i];
    }
    if (tid < NGRP) {
        int gi = dil_idx * NGRP + tid;
        float inv = bn_gamma[gi] * rsqrtf(bn_var[gi] + 1e-5f);
        s_sc[tid] = inv;
        s_sh[tid] = (conv_b[gi] - bn_mean[gi]) * inv + bn_beta[gi];
    }

    // Prologue: async-stage gin=0 slab into buffer 0
#pragma unroll
    for (int k = 0; k < SLAB_LD; k++) {
        int i = tid + k * 256;
        if (i < SLAB)
            cp_async4(s_in_addr + (uint32_t)i * 4,
                      costz + (gofs[k] >= 0 ? gofs[k] : 0),
                      gofs[k] >= 0 ? 4 : 0);
    }
    asm volatile("cp.async.commit_group;");

    // Accumulators: 4 rows x 16 gout (8 f32x2 pairs per row -> grouped as 4x4)
    unsigned long long acc[4][8];
#pragma unroll
    for (int i = 0; i < 4; i++)
#pragma unroll
        for (int p = 0; p < 8; p++) acc[i][p] = 0ull;

    const int r0 = ty * 4;

#pragma unroll 1
    for (int gin = 0; gin < NGRP; gin++) {
        if (gin < NGRP - 1) {
            // Issue next gin slab into the other buffer
            const float* __restrict__ src = costz + (size_t)(gin + 1) * NPHW;
            uint32_t dst = s_in_addr + (uint32_t)(((gin + 1) & 1) * SLAB) * 4;
#pragma unroll
            for (int k = 0; k < SLAB_LD; k++) {
                int i = tid + k * 256;
                if (i < SLAB)
                    cp_async4(dst + (uint32_t)i * 4,
                              src + (gofs[k] >= 0 ? gofs[k] : 0),
                              gofs[k] >= 0 ? 4 : 0);
            }
            asm volatile("cp.async.commit_group;");
            asm volatile("cp.async.wait_group 1;");
        } else {
            asm volatile("cp.async.wait_group 0;");
        }
        __syncthreads();

        const float* __restrict__ in_g = s_in + (gin & 1) * SLAB;
        const float* __restrict__ w_g  = s_w + gin * 27 * NGRP;

#pragma unroll
        for (int kd = 0; kd < 3; kd++) {
#pragma unroll
            for (int kw = 0; kw < 3; kw++) {
                // 6 input rows cover kh-rotation for 4 output rows
                unsigned long long vv[6];
#pragma unroll
                for (int j = 0; j < 6; j++)
                    vv[j] = pack_dup(
                        in_g[kd * (SIN_H * SIN_W) + (r0 + j) * SIN_W + tx + kw]);
#pragma unroll
                for (int kh = 0; kh < 3; kh++) {
                    const ulonglong2* wp = (const ulonglong2*)(
                        w_g + (kd * 9 + kh * 3 + kw) * NGRP);
                    ulonglong2 w0 = wp[0];
                    ulonglong2 w1 = wp[1];
#pragma unroll
                    for (int i = 0; i < 4; i++) {
                        unsigned long long v = vv[i + kh];
                        acc[i][0] = ffma2(v, w0.x, acc[i][0]);
                        acc[i][1] = ffma2(v, w0.y, acc[i][1]);
                        acc[i][2] = ffma2(v, w1.x, acc[i][2]);
                        acc[i][3] = ffma2(v, w1.y, acc[i][3]);
                        // second half of gout (pairs 4..7) via next 16B
                        ulonglong2 w2 = wp[2];
                        ulonglong2 w3 = wp[3];
                        acc[i][4] = ffma2(v, w2.x, acc[i][4]);
                        acc[i][5] = ffma2(v, w2.y, acc[i][5]);
                        acc[i][6] = ffma2(v, w3.x, acc[i][6]);
                        acc[i][7] = ffma2(v, w3.y, acc[i][7]);
                    }
                }
            }
        }
        __syncthreads();
    }

    // Epilogue: BN scale/shift + ReLU
    float sc[NGRP], sh[NGRP];
#pragma unroll
    for (int g = 0; g < NGRP; g++) { sc[g] = s_sc[g]; sh[g] = s_sh[g]; }

    const size_t ob0 =
        ((size_t)(b * (NDIL * NGRP) + dil_idx * NGRP) * NP + d) * HW + tx;
#pragma unroll
    for (int i = 0; i < 4; i++) {
        const int h = h0 + r0 + i;
        const size_t ob = ob0 + (size_t)h * WW;
#pragma unroll
        for (int p = 0; p < 8; p++) {
            float lo, hi;
            asm("mov.b64 {%0, %1}, %2;" : "=f"(lo), "=f"(hi) : "l"(acc[i][p]));
            out[ob + (size_t)(2 * p) * NPHW] =
                fmaxf(lo * sc[2 * p] + sh[2 * p], 0.f);
            out[ob + (size_t)(2 * p + 1) * NPHW] =
                fmaxf(hi * sc[2 * p + 1] + sh[2 * p + 1], 0.f);
        }
    }
}

#define SMEM_BYTES ((2 * SLAB + SW_ELEMS + 2 * NGRP) * 4)

// ---------------------------------------------------------------------------
extern "C" void kernel_launch(void* const* d_in, const int* in_sizes, int n_in,
                              void* d_out, int out_size) {
    const float* x  = (const float*)d_in[0];
    const float* nb = (const float*)d_in[1];
    const float* cw = (const float*)d_in[2];
    const float* cb = (const float*)d_in[3];
    const float* gm = (const float*)d_in[4];
    const float* bt = (const float*)d_in[5];
    const float* mn = (const float*)d_in[6];
    const float* vr = (const float*)d_in[7];
    float* out = (float*)d_out;

    dim3 cb1(64, 4);
    dim3 cg1(HH / 4, NGRP, NDIL * BATCH);
    corr_kernel<<<cg1, cb1>>>(x, nb);

    cudaFuncSetAttribute(conv_kernel,
                         cudaFuncAttributeMaxDynamicSharedMemorySize,
                         SMEM_BYTES);
    dim3 cg2(1, HH / TILE_H, NDIL * BATCH * NP);
    conv_kernel<<<cg2, dim3(64, 4), SMEM_BYTES>>>(cw, cb, gm, bt, mn, vr, out);
}

// round 4
// speedup vs baseline: 2.1398x; 1.0111x over previous
#include <cuda_runtime.h>
#include <cstdint>

// Problem constants
#define BATCH 2
#define CHAN  128
#define NGRP  16
#define CPG   8
#define HH    64
#define WW    64
#define HW    (HH*WW)
#define NP    81
#define NDIL  4
#define NPHW  (NP*HW)

// Conv tiling: 16 rows x 64 wide per block; thread = 4 contiguous rows x 1 col
#define TILE_H 16
#define SIN_H  (TILE_H + 2)          // 18
#define SIN_W  (WW + 2)              // 66
#define SLAB   (3 * SIN_H * SIN_W)   // 3564 floats per gin slab
#define SLAB_LD 14                   // ceil(3564/256)
#define NBUF   4                     // slab ring depth
#define SW_ELEMS (NGRP * NGRP * 27)  // 6912

// Scratch cost volume: [dil*b][g][disp][h][w] ~170MB
__device__ float g_cost[(size_t)NDIL * BATCH * NGRP * NPHW];

// ---- packed fp32x2 helpers ----
__device__ __forceinline__ unsigned long long pack_dup(float v) {
    unsigned long long r;
    asm("mov.b64 %0, {%1, %1};" : "=l"(r) : "f"(v));
    return r;
}
__device__ __forceinline__ unsigned long long ffma2(
    unsigned long long a, unsigned long long b, unsigned long long c) {
    unsigned long long d;
    asm("fma.rn.f32x2 %0, %1, %2, %3;" : "=l"(d) : "l"(a), "l"(b), "l"(c));
    return d;
}
__device__ __forceinline__ uint32_t smem_u32(const void* p) {
    uint32_t a;
    asm("{ .reg .u64 t; cvta.to.shared.u64 t, %1; cvt.u32.u64 %0, t; }"
        : "=r"(a) : "l"(p));
    return a;
}
__device__ __forceinline__ void cp_async4(uint32_t dst, const float* src, int sz) {
    asm volatile("cp.async.ca.shared.global [%0], [%1], 4, %2;"
                 :: "r"(dst), "l"(src), "r"(sz));
}

// ---------------------------------------------------------------------------
// Kernel 1: grouped windowed correlation + leaky ReLU(0.1)
// ---------------------------------------------------------------------------
__global__ void corr_kernel(const float* __restrict__ x,
                            const float* __restrict__ nb) {
    const int w  = threadIdx.x;
    const int h  = blockIdx.x * 4 + threadIdx.y;
    const int g  = blockIdx.y;
    const int zb = blockIdx.z;
    const int b  = zb & 1;
    const int dil = 1 << (zb >> 1);

    float a1[CPG];
#pragma unroll
    for (int c = 0; c < CPG; c++)
        a1[c] = x[(size_t)(b * CHAN + c * NGRP + g) * HW + h * WW + w];

    const float* __restrict__ x2b = nb + (size_t)b * CHAN * HW;
    float* __restrict__ outp =
        g_cost + ((size_t)(zb * NGRP + g) * NP) * HW + h * WW + w;

#pragma unroll 1
    for (int di = 0; di < 9; di++) {
        const int y = h + (di - 4) * dil;
        const bool yok = ((unsigned)y < HH);
#pragma unroll 1
        for (int dj = 0; dj < 9; dj++) {
            const int xw = w + (dj - 4) * dil;
            float s = 0.f;
            if (yok && (unsigned)xw < WW) {
                const int off = y * WW + xw;
#pragma unroll
                for (int c = 0; c < CPG; c++)
                    s += a1[c] * x2b[(size_t)(c * NGRP + g) * HW + off];
            }
            s = (s > 0.f) ? s : 0.1f * s;
            outp[(size_t)(di * 9 + dj) * HW] = s;
        }
    }
}

// ---------------------------------------------------------------------------
// Kernel 2: 3x3x3 grouped conv (16->16) + bias + BN + ReLU
// f32x2 accumulators, 4 rows/thread with kh rotation, quad-buffered cp.async
// pipeline with ONE barrier per gin, fully hoisted weight vectors.
// grid: (1, HH/TILE_H=4, NDIL*BATCH*NP=648), block (64,4)=256
// ---------------------------------------------------------------------------
__global__ void __launch_bounds__(256, 2)
conv_kernel(const float* __restrict__ conv_w,
            const float* __restrict__ conv_b,
            const float* __restrict__ bn_gamma,
            const float* __restrict__ bn_beta,
            const float* __restrict__ bn_mean,
            const float* __restrict__ bn_var,
            float* __restrict__ out) {
    extern __shared__ float sm[];
    float* s_in = sm;                    // [NBUF][SLAB]
    float* s_w  = sm + NBUF * SLAB;      // [gin*27+tap][16 gout]
    float* s_sc = s_w + SW_ELEMS;
    float* s_sh = s_sc + NGRP;

    const int tx  = threadIdx.x;         // 0..63
    const int ty  = threadIdx.y;         // 0..3
    const int tid = ty * 64 + tx;
    const int zb  = blockIdx.z;
    const int dil_idx = zb / (BATCH * NP);
    const int rem = zb % (BATCH * NP);
    const int b   = rem / NP;
    const int d   = rem % NP;
    const int h0  = blockIdx.y * TILE_H;

    const float* __restrict__ costz =
        g_cost + (size_t)(dil_idx * BATCH + b) * NGRP * NPHW;

    // Per-thread staging offsets (same for every gin slab)
    int gofs[SLAB_LD];
#pragma unroll
    for (int k = 0; k < SLAB_LD; k++) {
        int i = tid + k * 256;
        int ofs = -1;
        if (i < SLAB) {
            int kd = i / (SIN_H * SIN_W);
            int r  = i - kd * (SIN_H * SIN_W);
            int hi = r / SIN_W;
            int wi = r - hi * SIN_W;
            int dg = d + kd - 1;
            int hg = h0 + hi - 1;
            int wg = wi - 1;
            if ((unsigned)dg < NP && (unsigned)hg < HH && (unsigned)wg < WW)
                ofs = dg * HW + hg * WW + wg;
        }
        gofs[k] = ofs;
    }
    uint32_t s_in_addr = smem_u32(s_in);

    // Stage weights transposed: [gin*27+tap][gout]
    const float* __restrict__ wsrc = conv_w + (size_t)dil_idx * SW_ELEMS;
    for (int i = tid; i < SW_ELEMS; i += 256) {
        int gout = i / (NGRP * 27);
        int gt   = i - gout * (NGRP * 27);
        s_w[gt * NGRP + gout] = wsrc[i];
    }
    if (tid < NGRP) {
        int gi = dil_idx * NGRP + tid;
        float inv = bn_gamma[gi] * rsqrtf(bn_var[gi] + 1e-5f);
        s_sc[tid] = inv;
        s_sh[tid] = (conv_b[gi] - bn_mean[gi]) * inv + bn_beta[gi];
    }

    // Prologue: async-stage slabs for gin=0 and gin=1 (two groups)
#pragma unroll 1
    for (int g0 = 0; g0 < 2; g0++) {
        const float* __restrict__ src = costz + (size_t)g0 * NPHW;
        uint32_t dst = s_in_addr + (uint32_t)(g0 * SLAB) * 4;
#pragma unroll
        for (int k = 0; k < SLAB_LD; k++) {
            int i = tid + k * 256;
            if (i < SLAB)
                cp_async4(dst + (uint32_t)i * 4,
                          src + (gofs[k] >= 0 ? gofs[k] : 0),
                          gofs[k] >= 0 ? 4 : 0);
        }
        asm volatile("cp.async.commit_group;");
    }

    // Accumulators: 4 rows x 16 gout (8 f32x2 pairs per row)
    unsigned long long acc[4][8];
#pragma unroll
    for (int i = 0; i < 4; i++)
#pragma unroll
        for (int p = 0; p < 8; p++) acc[i][p] = 0ull;

    const int r0 = ty * 4;

#pragma unroll 1
    for (int gin = 0; gin < NGRP; gin++) {
        // Issue slab gin+2 into ring buffer (distance 2; never collides with
        // the slowest warp's reader at gin-1 since (gin+2)%4 != (gin-1)%4).
        if (gin + 2 < NGRP) {
            const float* __restrict__ src = costz + (size_t)(gin + 2) * NPHW;
            uint32_t dst = s_in_addr + (uint32_t)(((gin + 2) & 3) * SLAB) * 4;
#pragma unroll
            for (int k = 0; k < SLAB_LD; k++) {
                int i = tid + k * 256;
                if (i < SLAB)
                    cp_async4(dst + (uint32_t)i * 4,
                              src + (gofs[k] >= 0 ? gofs[k] : 0),
                              gofs[k] >= 0 ? 4 : 0);
            }
            asm volatile("cp.async.commit_group;");
            asm volatile("cp.async.wait_group 2;");
        } else if (gin + 2 == NGRP) {
            asm volatile("cp.async.wait_group 1;");
        } else {
            asm volatile("cp.async.wait_group 0;");
        }
        __syncthreads();   // single barrier per gin

        const float* __restrict__ in_g = s_in + (gin & 3) * SLAB;
        const float* __restrict__ w_g  = s_w + gin * 27 * NGRP;

#pragma unroll
        for (int kd = 0; kd < 3; kd++) {
#pragma unroll
            for (int kw = 0; kw < 3; kw++) {
                // 6 input rows cover the kh-rotation for 4 output rows
                unsigned long long vv[6];
#pragma unroll
                for (int j = 0; j < 6; j++)
                    vv[j] = pack_dup(
                        in_g[kd * (SIN_H * SIN_W) + (r0 + j) * SIN_W + tx + kw]);
#pragma unroll
                for (int kh = 0; kh < 3; kh++) {
                    const ulonglong2* wp = (const ulonglong2*)(
                        w_g + (kd * 9 + kh * 3 + kw) * NGRP);
                    // hoist ALL four weight vectors out of the row loop
                    const ulonglong2 w0 = wp[0];
                    const ulonglong2 w1 = wp[1];
                    const ulonglong2 w2 = wp[2];
                    const ulonglong2 w3 = wp[3];
#pragma unroll
                    for (int i = 0; i < 4; i++) {
                        const unsigned long long v = vv[i + kh];
                        acc[i][0] = ffma2(v, w0.x, acc[i][0]);
                        acc[i][1] = ffma2(v, w0.y, acc[i][1]);
                        acc[i][2] = ffma2(v, w1.x, acc[i][2]);
                        acc[i][3] = ffma2(v, w1.y, acc[i][3]);
                        acc[i][4] = ffma2(v, w2.x, acc[i][4]);
                        acc[i][5] = ffma2(v, w2.y, acc[i][5]);
                        acc[i][6] = ffma2(v, w3.x, acc[i][6]);
                        acc[i][7] = ffma2(v, w3.y, acc[i][7]);
                    }
                }
            }
        }
    }

    // Epilogue: BN scale/shift + ReLU
    float sc[NGRP], sh[NGRP];
#pragma unroll
    for (int g = 0; g < NGRP; g++) { sc[g] = s_sc[g]; sh[g] = s_sh[g]; }

    const size_t ob0 =
        ((size_t)(b * (NDIL * NGRP) + dil_idx * NGRP) * NP + d) * HW + tx;
#pragma unroll
    for (int i = 0; i < 4; i++) {
        const int h = h0 + r0 + i;
        const size_t ob = ob0 + (size_t)h * WW;
#pragma unroll
        for (int p = 0; p < 8; p++) {
            float lo, hi;
            asm("mov.b64 {%0, %1}, %2;" : "=f"(lo), "=f"(hi) : "l"(acc[i][p]));
            out[ob + (size_t)(2 * p) * NPHW] =
                fmaxf(lo * sc[2 * p] + sh[2 * p], 0.f);
            out[ob + (size_t)(2 * p + 1) * NPHW] =
                fmaxf(hi * sc[2 * p + 1] + sh[2 * p + 1], 0.f);
        }
    }
}

#define SMEM_BYTES ((NBUF * SLAB + SW_ELEMS + 2 * NGRP + 16) * 4)

// ---------------------------------------------------------------------------
extern "C" void kernel_launch(void* const* d_in, const int* in_sizes, int n_in,
                              void* d_out, int out_size) {
    const float* x  = (const float*)d_in[0];
    const float* nb = (const float*)d_in[1];
    const float* cw = (const float*)d_in[2];
    const float* cb = (const float*)d_in[3];
    const float* gm = (const float*)d_in[4];
    const float* bt = (const float*)d_in[5];
    const float* mn = (const float*)d_in[6];
    const float* vr = (const float*)d_in[7];
    float* out = (float*)d_out;

    dim3 cb1(64, 4);
    dim3 cg1(HH / 4, NGRP, NDIL * BATCH);
    corr_kernel<<<cg1, cb1>>>(x, nb);

    cudaFuncSetAttribute(conv_kernel,
                         cudaFuncAttributeMaxDynamicSharedMemorySize,
                         SMEM_BYTES);
    dim3 cg2(1, HH / TILE_H, NDIL * BATCH * NP);
    conv_kernel<<<cg2, dim3(64, 4), SMEM_BYTES>>>(cw, cb, gm, bt, mn, vr, out);
}